// round 7
// baseline (speedup 1.0000x reference)
#include <cuda_runtime.h>
#include <cuda_bf16.h>

typedef unsigned long long u64;

#define T_N 4096

// ---- shared layout (float word offsets), dynamic smem ----
#define SWI   0        // Wi1: [3 dots][128 jk][8] = 3072
#define H1B   3072     // [2 slot][2 b][72] = 288
#define H2B   3360     // 288
#define O1B   3648     // ring [32][2][72] = 4608
#define XBUF  8256     // ring [32][2][16] = 1024
#define XI1B  9280     // ring [16][2][196] = 6272
#define XI2B  15552    // ring [16][2][196] = 6272
#define XPB   21824    // ring [16][2][68] = 2176
#define SCB   24000    // [2 slot][2 b][4 wg] = 16
#define SATT  24016    // [2][64] = 128
#define SM1   24144    // 256
#define SM2   24400    // 128
#define SM3   24528    // 64
#define STOT  24592    // 98368 bytes

#define NBAR(id) asm volatile("bar.sync %0, %1;" :: "r"(id), "r"(128) : "memory")

__device__ __forceinline__ void ffma2(u64 &d, u64 a, u64 b) {
    asm("fma.rn.f32x2 %0, %1, %2, %0;" : "+l"(d) : "l"(a), "l"(b));
}
__device__ __forceinline__ u64 pack2(float lo, float hi) {
    u64 r; asm("mov.b64 %0, {%1, %2};" : "=l"(r) : "f"(lo), "f"(hi)); return r;
}
__device__ __forceinline__ float hsum2(u64 a) {
    float lo, hi;
    asm("mov.b64 {%0, %1}, %2;" : "=f"(lo), "=f"(hi) : "l"(a));
    return lo + hi;
}
// lane kc finalizes batch kc: keep own-batch partial, exchange partner's
__device__ __forceinline__ float xred(float b0, float b1, int kc) {
    float keep = kc ? b1 : b0;
    float send = kc ? b0 : b1;
    return keep + __shfl_xor_sync(0xffffffffu, send, 1);
}
__device__ __forceinline__ float sigf(float v)     { return __fdividef(1.f, 1.f + __expf(-v)); }
__device__ __forceinline__ float tanhfast(float v) { return 1.f - __fdividef(2.f, __expf(2.f * v) + 1.f); }

// 3 matrices x 2 batches, k-half (32) per thread, weights in registers.
// v: [b0 72][b1 72] state slot; kc36 = kc*36.
__device__ __forceinline__ void dot6(const u64 (&wa)[16], const u64 (&wb)[16], const u64 (&wc)[16],
                                     const float* v, int kc36,
                                     u64 &a0, u64 &a1, u64 &a2, u64 &c0, u64 &c1, u64 &c2)
{
    const ulonglong2* h0 = reinterpret_cast<const ulonglong2*>(v + kc36);
    const ulonglong2* h1 = reinterpret_cast<const ulonglong2*>(v + 72 + kc36);
#pragma unroll
    for (int m = 0; m < 8; ++m) {
        ulonglong2 x0 = h0[m], x1 = h1[m];
        ffma2(a0, wa[2*m], x0.x); ffma2(a0, wa[2*m+1], x0.y);
        ffma2(a1, wb[2*m], x0.x); ffma2(a1, wb[2*m+1], x0.y);
        ffma2(a2, wc[2*m], x0.x); ffma2(a2, wc[2*m+1], x0.y);
        ffma2(c0, wa[2*m], x1.x); ffma2(c0, wa[2*m+1], x1.y);
        ffma2(c1, wb[2*m], x1.x); ffma2(c1, wb[2*m+1], x1.y);
        ffma2(c2, wc[2*m], x1.x); ffma2(c2, wc[2*m+1], x1.y);
    }
}

extern __shared__ float sm[];

__global__ __launch_bounds__(384, 1)
void solar_fused(const float* __restrict__ x,
                 const float* __restrict__ Wi1,  const float* __restrict__ bi1,
                 const float* __restrict__ Whr1, const float* __restrict__ Whz1,
                 const float* __restrict__ Whn1, const float* __restrict__ bhn1,
                 const float* __restrict__ Wi2,  const float* __restrict__ bi2,
                 const float* __restrict__ Whr2, const float* __restrict__ Whz2,
                 const float* __restrict__ Whn2, const float* __restrict__ bhn2,
                 const float* __restrict__ Wp,   const float* __restrict__ bp,
                 const float* __restrict__ Wa,   const float* __restrict__ ba,
                 const float* __restrict__ W1,   const float* __restrict__ b1,
                 const float* __restrict__ W2,   const float* __restrict__ b2,
                 const float* __restrict__ W3,   const float* __restrict__ b3,
                 const float* __restrict__ W4,   const float* __restrict__ b4,
                 float* __restrict__ out)
{
    const int tid  = threadIdx.x;
    const int grp  = tid >> 7;       // 0: L1-GRU, 1: xi1/xi2/xp/loader, 2: L2-GRU+attn
    const int g    = tid & 127;
    const int j    = g >> 1;         // 0..63
    const int kc   = g & 1;          // k-half / finalized batch
    const int kc8  = kc * 8;
    const int kc36 = kc * 36;
    const int lane = tid & 31;
    const int wg   = g >> 5;         // warp within group 0..3
    const int widx = kc * 72 + (j >> 5) * 36 + (j & 31); // (batch kc, elem j)

    // ---------- register-resident weights ----------
    u64 wA[16], wB[16], wC[16], wD[4];
    float cb0 = 0.f, cb1 = 0.f, cb2 = 0.f, cb3 = 0.f;
    float cd0 = 0.f, cd1 = 0.f, cd2 = 0.f;
    float cwa = 0.f, cba = 0.f;
    if (grp == 0) {
#pragma unroll
        for (int m = 0; m < 16; ++m) {
            int k = kc * 32 + 2 * m;
            wA[m] = pack2(Whr1[k*64 + j], Whr1[(k+1)*64 + j]);
            wB[m] = pack2(Whz1[k*64 + j], Whz1[(k+1)*64 + j]);
            wC[m] = pack2(Whn1[k*64 + j], Whn1[(k+1)*64 + j]);
        }
        cb3 = bhn1[j];
    } else if (grp == 1) {
#pragma unroll
        for (int m = 0; m < 16; ++m) {
            int k = kc * 32 + 2 * m;
            wA[m] = pack2(Wi2[k*192 + j],       Wi2[(k+1)*192 + j]);
            wB[m] = pack2(Wi2[k*192 + 64 + j],  Wi2[(k+1)*192 + 64 + j]);
            wC[m] = pack2(Wi2[k*192 + 128 + j], Wi2[(k+1)*192 + 128 + j]);
        }
#pragma unroll
        for (int m = 0; m < 4; ++m) {
            int f = kc * 8 + 2 * m;
            wD[m] = pack2(Wp[f*64 + j], Wp[(f+1)*64 + j]);
        }
        cb0 = bi2[j]; cb1 = bi2[64 + j]; cb2 = bi2[128 + j]; cb3 = bp[j];
        cd0 = bi1[j]; cd1 = bi1[64 + j]; cd2 = bi1[128 + j];
    } else {
#pragma unroll
        for (int m = 0; m < 16; ++m) {
            int k = kc * 32 + 2 * m;
            wA[m] = pack2(Whr2[k*64 + j], Whr2[(k+1)*64 + j]);
            wB[m] = pack2(Whz2[k*64 + j], Whz2[(k+1)*64 + j]);
            wC[m] = pack2(Whn2[k*64 + j], Whn2[(k+1)*64 + j]);
        }
        cb0 = bhn2[j]; cwa = Wa[j]; cba = ba[0];
    }

    // ---------- shared setup: Wi1 + zero state ----------
    for (int idx = tid; idx < 3072; idx += 384) {      // [dot][j*2+kc][8]
        int d = idx >> 10, rem = idx & 1023;
        int jk = rem >> 3, fl = rem & 7;
        sm[SWI + idx] = Wi1[((jk & 1) * 8 + fl) * 192 + d * 64 + (jk >> 1)];
    }
    for (int idx = tid; idx < 576; idx += 384) sm[H1B + idx] = 0.f;   // h1+h2 both slots
    __syncthreads();

    // ---------- x prologue: t=0..15 into xbuf, rx = x[16] ----------
    float rx = 0.f;
    size_t xbase = 0;
    if (grp == 1 && g < 32) {
        int b = g >> 4, f = g & 15;
        int bg = blockIdx.x * 2 + b;
        xbase = (size_t)bg * T_N * 16 + f;
#pragma unroll
        for (int t = 0; t < 16; ++t) sm[XBUF + t * 32 + b * 16 + f] = x[xbase + (size_t)t * 16];
        rx = x[xbase + 256];                           // t=16
    }
    __syncthreads();

    // ---------- xi1/xp prologue for t=0..7 (group 1) ----------
    if (grp == 1) {
        for (int tt = 0; tt < 8; ++tt) {
            const float* xb = sm + XBUF + tt * 32;
            const ulonglong2* x0p = reinterpret_cast<const ulonglong2*>(xb + kc8);
            const ulonglong2* x1p = reinterpret_cast<const ulonglong2*>(xb + 16 + kc8);
            const ulonglong2* wiR = reinterpret_cast<const ulonglong2*>(sm + SWI + (j*2+kc)*8);
            const ulonglong2* wiZ = reinterpret_cast<const ulonglong2*>(sm + SWI + 1024 + (j*2+kc)*8);
            const ulonglong2* wiN = reinterpret_cast<const ulonglong2*>(sm + SWI + 2048 + (j*2+kc)*8);
            u64 r0=0, z0=0, n0=0, r1=0, z1=0, n1=0, p0=0, p1=0;
#pragma unroll
            for (int m = 0; m < 2; ++m) {
                ulonglong2 xa = x0p[m], xc = x1p[m];
                ulonglong2 wr = wiR[m], wz = wiZ[m], wn = wiN[m];
                ffma2(r0, wr.x, xa.x); ffma2(r0, wr.y, xa.y);
                ffma2(z0, wz.x, xa.x); ffma2(z0, wz.y, xa.y);
                ffma2(n0, wn.x, xa.x); ffma2(n0, wn.y, xa.y);
                ffma2(r1, wr.x, xc.x); ffma2(r1, wr.y, xc.y);
                ffma2(z1, wz.x, xc.x); ffma2(z1, wz.y, xc.y);
                ffma2(n1, wn.x, xc.x); ffma2(n1, wn.y, xc.y);
                ffma2(p0, wD[2*m], xa.x); ffma2(p0, wD[2*m+1], xa.y);
                ffma2(p1, wD[2*m], xc.x); ffma2(p1, wD[2*m+1], xc.y);
            }
            int s = tt & 15;
            int base = XI1B + s * 392 + kc * 196;
            sm[base + j]       = xred(hsum2(r0), hsum2(r1), kc) + cd0;
            sm[base + 64 + j]  = xred(hsum2(z0), hsum2(z1), kc) + cd1;
            sm[base + 128 + j] = xred(hsum2(n0), hsum2(n1), kc) + cd2;
            sm[XPB + s * 136 + kc * 68 + j] = xred(hsum2(p0), hsum2(p1), kc) + cb3;
        }
    }
    __syncthreads();

    // ---------- recurrence: g0 @ t=i, g1: xi2@t=i-8 & xi1/xp@t=i+8, g2 @ t=i-16 ----------
    float am = -3.0e38f, as_ = 0.f, aacc = 0.f, po2 = 0.f;

#pragma unroll 1
    for (int i = 0; i <= T_N + 16; ++i) {
        if (grp == 0) {
            if (i < T_N) {
                int slot = i & 1;
                const float* hv = sm + H1B + slot * 144;
                u64 r0=0, z0=0, nh0=0, r1=0, z1=0, nh1=0;
                dot6(wA, wB, wC, hv, kc36, r0, z0, nh0, r1, z1, nh1);
                float fR  = xred(hsum2(r0),  hsum2(r1),  kc);
                float fZ  = xred(hsum2(z0),  hsum2(z1),  kc);
                float fNH = xred(hsum2(nh0), hsum2(nh1), kc);
                int s = i & 15;
                int xb1 = XI1B + s * 392 + kc * 196;
                float ir = sm[xb1 + j], iz = sm[xb1 + 64 + j], inn = sm[xb1 + 128 + j];
                float r  = sigf(fR + ir);
                float z  = sigf(fZ + iz);
                float n  = tanhfast(inn + r * (fNH + cb3));
                float hp = sm[H1B + slot * 144 + widx];
                float hn = n + z * (hp - n);
                float xp = sm[XPB + s * 136 + kc * 68 + j];
                sm[H1B + (slot ^ 1) * 144 + widx] = hn;
                sm[O1B + (i & 31) * 144 + widx]   = hn + 0.5f * xp;
            }
            NBAR(1);
        } else if (grp == 1) {
            if (i >= 8 && i <= T_N + 7) {     // xi2[t=i-8] = o1[i-8] @ Wi2 + bi2
                const float* ov = sm + O1B + ((i + 24) & 31) * 144;
                u64 a0=0, a1=0, a2=0, c0=0, c1=0, c2=0;
                dot6(wA, wB, wC, ov, kc36, a0, a1, a2, c0, c1, c2);
                int s2 = (i + 8) & 15;
                int base = XI2B + s2 * 392 + kc * 196;
                sm[base + j]       = xred(hsum2(a0), hsum2(c0), kc) + cb0;
                sm[base + 64 + j]  = xred(hsum2(a1), hsum2(c1), kc) + cb1;
                sm[base + 128 + j] = xred(hsum2(a2), hsum2(c2), kc) + cb2;
            }
            if (i <= T_N - 9) {               // xi1/xp for t=i+8
                const float* xb = sm + XBUF + ((i + 8) & 31) * 32;
                const ulonglong2* x0p = reinterpret_cast<const ulonglong2*>(xb + kc8);
                const ulonglong2* x1p = reinterpret_cast<const ulonglong2*>(xb + 16 + kc8);
                const ulonglong2* wiR = reinterpret_cast<const ulonglong2*>(sm + SWI + (j*2+kc)*8);
                const ulonglong2* wiZ = reinterpret_cast<const ulonglong2*>(sm + SWI + 1024 + (j*2+kc)*8);
                const ulonglong2* wiN = reinterpret_cast<const ulonglong2*>(sm + SWI + 2048 + (j*2+kc)*8);
                u64 r0=0, z0=0, n0=0, r1=0, z1=0, n1=0, p0=0, p1=0;
#pragma unroll
                for (int m = 0; m < 2; ++m) {
                    ulonglong2 xa = x0p[m], xc = x1p[m];
                    ulonglong2 wr = wiR[m], wz = wiZ[m], wn = wiN[m];
                    ffma2(r0, wr.x, xa.x); ffma2(r0, wr.y, xa.y);
                    ffma2(z0, wz.x, xa.x); ffma2(z0, wz.y, xa.y);
                    ffma2(n0, wn.x, xa.x); ffma2(n0, wn.y, xa.y);
                    ffma2(r1, wr.x, xc.x); ffma2(r1, wr.y, xc.y);
                    ffma2(z1, wz.x, xc.x); ffma2(z1, wz.y, xc.y);
                    ffma2(n1, wn.x, xc.x); ffma2(n1, wn.y, xc.y);
                    ffma2(p0, wD[2*m], xa.x); ffma2(p0, wD[2*m+1], xa.y);
                    ffma2(p1, wD[2*m], xc.x); ffma2(p1, wD[2*m+1], xc.y);
                }
                int s = (i + 8) & 15;
                int base = XI1B + s * 392 + kc * 196;
                sm[base + j]       = xred(hsum2(r0), hsum2(r1), kc) + cd0;
                sm[base + 64 + j]  = xred(hsum2(z0), hsum2(z1), kc) + cd1;
                sm[base + 128 + j] = xred(hsum2(n0), hsum2(n1), kc) + cd2;
                sm[XPB + s * 136 + kc * 68 + j] = xred(hsum2(p0), hsum2(p1), kc) + cb3;
            }
            if (g < 32) {                     // x stream: store t=i+16, prefetch t=i+17
                if (i <= T_N - 17) sm[XBUF + ((i + 16) & 31) * 32 + (g >> 4) * 16 + (g & 15)] = rx;
                if (i <= T_N - 18) rx = x[xbase + (size_t)(i + 17) * 16];
            }
            // no barrier: group 1 has no intra-group step dependencies
        } else {
            if (i >= 17) {                    // online softmax for t = i-17
                float4 sp = *reinterpret_cast<const float4*>(sm + SCB + ((i - 1) & 1) * 8 + kc * 4);
                float sc   = (sp.x + sp.y) + (sp.z + sp.w) + cba;
                float nm   = fmaxf(am, sc);
                float corr = __expf(am - nm);
                float p    = __expf(sc - nm);
                as_  = as_  * corr + p;
                aacc = aacc * corr + p * po2;
                am   = nm;
            }
            if (i >= 16 && i <= T_N + 15) {   // layer-2 GRU for t = i-16
                int hs = i & 1;
                const float* hv = sm + H2B + hs * 144;
                u64 a0=0, a1=0, a2=0, c0=0, c1=0, c2=0;
                dot6(wA, wB, wC, hv, kc36, a0, a1, a2, c0, c1, c2);
                float fR  = xred(hsum2(a0), hsum2(c0), kc);
                float fZ  = xred(hsum2(a1), hsum2(c1), kc);
                float fNH = xred(hsum2(a2), hsum2(c2), kc);
                int xb2 = XI2B + (i & 15) * 392 + kc * 196;
                float ir = sm[xb2 + j], iz = sm[xb2 + 64 + j], inn = sm[xb2 + 128 + j];
                float hp = sm[H2B + hs * 144 + widx];
                float r  = sigf(ir + fR);
                float z  = sigf(iz + fZ);
                float n  = tanhfast(inn + r * (fNH + cb0));
                float hn = n + z * (hp - n);
                float o1r = sm[O1B + ((i + 16) & 31) * 144 + widx];
                float o2  = hn + 0.5f * o1r;
                po2 = o2;
                sm[H2B + (hs ^ 1) * 144 + widx] = hn;
                float part = o2 * cwa;        // score partial for batch kc
                part += __shfl_xor_sync(0xffffffffu, part, 2);
                part += __shfl_xor_sync(0xffffffffu, part, 4);
                part += __shfl_xor_sync(0xffffffffu, part, 8);
                part += __shfl_xor_sync(0xffffffffu, part, 16);
                if (lane < 2) sm[SCB + (i & 1) * 8 + kc * 4 + wg] = part;
            }
            NBAR(3);
        }
        if ((i & 7) == 7) __syncthreads();
    }
    __syncthreads();

    // ---------- attention finalize + MLP head ----------
    if (grp == 2) sm[SATT + kc * 64 + j] = aacc / as_;
    __syncthreads();

    if (tid < 256) {
        int b = tid >> 7, o = tid & 127;
        float acc = b1[o];
        const float* av = sm + SATT + b * 64;
#pragma unroll 8
        for (int k = 0; k < 64; ++k) acc += av[k] * W1[k * 128 + o];
        sm[SM1 + b * 128 + o] = fmaxf(acc, 0.f);
    }
    __syncthreads();
    if (tid < 128) {
        int b = tid >> 6, o = tid & 63;
        float acc = b2[o];
        const float* av = sm + SM1 + b * 128;
#pragma unroll 8
        for (int k = 0; k < 128; ++k) acc += av[k] * W2[k * 64 + o];
        sm[SM2 + b * 64 + o] = fmaxf(acc, 0.f);
    }
    __syncthreads();
    if (tid < 64) {
        int b = tid >> 5, o = tid & 31;
        float acc = b3[o];
        const float* av = sm + SM2 + b * 64;
#pragma unroll 8
        for (int k = 0; k < 64; ++k) acc += av[k] * W3[k * 32 + o];
        sm[SM3 + b * 32 + o] = fmaxf(acc, 0.f);
    }
    __syncthreads();
    if (tid < 4) {
        int b = tid >> 1, o = tid & 1;
        float acc = b4[o];
        const float* av = sm + SM3 + b * 32;
#pragma unroll
        for (int k = 0; k < 32; ++k) acc += av[k] * W4[k * 2 + o];
        out[((size_t)blockIdx.x * 2 + b) * 2 + o] = acc;
    }
}

extern "C" void kernel_launch(void* const* d_in, const int* in_sizes, int n_in,
                              void* d_out, int out_size) {
    (void)in_sizes; (void)n_in; (void)out_size;
    const float* x    = (const float*)d_in[0];
    const float* Wi1  = (const float*)d_in[1];
    const float* bi1  = (const float*)d_in[2];
    const float* Whr1 = (const float*)d_in[3];
    const float* Whz1 = (const float*)d_in[4];
    const float* Whn1 = (const float*)d_in[5];
    const float* bhn1 = (const float*)d_in[6];
    const float* Wi2  = (const float*)d_in[7];
    const float* bi2  = (const float*)d_in[8];
    const float* Whr2 = (const float*)d_in[9];
    const float* Whz2 = (const float*)d_in[10];
    const float* Whn2 = (const float*)d_in[11];
    const float* bhn2 = (const float*)d_in[12];
    const float* Wp   = (const float*)d_in[13];
    const float* bp   = (const float*)d_in[14];
    const float* Wa   = (const float*)d_in[15];
    const float* ba   = (const float*)d_in[16];
    const float* W1   = (const float*)d_in[17];
    const float* b1   = (const float*)d_in[18];
    const float* W2   = (const float*)d_in[19];
    const float* b2   = (const float*)d_in[20];
    const float* W3   = (const float*)d_in[21];
    const float* b3   = (const float*)d_in[22];
    const float* W4   = (const float*)d_in[23];
    const float* b4   = (const float*)d_in[24];
    float* out = (float*)d_out;

    static bool attr_set = false;
    if (!attr_set) {
        cudaFuncSetAttribute(solar_fused, cudaFuncAttributeMaxDynamicSharedMemorySize, STOT * 4);
        attr_set = true;
    }
    solar_fused<<<128, 384, STOT * 4>>>(x, Wi1, bi1, Whr1, Whz1, Whn1, bhn1,
                                        Wi2, bi2, Whr2, Whz2, Whn2, bhn2,
                                        Wp, bp, Wa, ba,
                                        W1, b1, W2, b2, W3, b3, W4, b4, out);
}

// round 9
// speedup vs baseline: 1.0579x; 1.0579x over previous
#include <cuda_runtime.h>
#include <cuda_bf16.h>

typedef unsigned long long u64;

#define T_N 4096

// ---- shared layout (float word offsets) ----
#define SWI   0        // Wi1: [3 dots][128 jk][8] = 3072
#define H1B   3072     // [2 slot][2 b][72] = 288
#define H2B   3360     // 288
#define O1B   3648     // ring [16 slot][2 b][72] = 2304
#define XBUF  5952     // [16 slot][2 b][16] = 512
#define XI2B  6464     // [8 slot][2 b][196 pad] = 3136
#define XPB   9600     // [8 slot][2 b][68 pad] = 1088
#define SCB   10688    // [2 slot][2 b][4 wg] = 16
#define SATT  10704    // [2][64] = 128
#define SM1   10832    // 256
#define SM2   11088    // 128
#define SM3   11216    // 64
#define STOT  11280

#define NBAR(id) asm volatile("bar.sync %0, %1;" :: "r"(id), "r"(128) : "memory")

__device__ __forceinline__ void ffma2(u64 &d, u64 a, u64 b) {
    asm("fma.rn.f32x2 %0, %1, %2, %0;" : "+l"(d) : "l"(a), "l"(b));
}
__device__ __forceinline__ u64 pack2(float lo, float hi) {
    u64 r; asm("mov.b64 %0, {%1, %2};" : "=l"(r) : "f"(lo), "f"(hi)); return r;
}
__device__ __forceinline__ float hsum2(u64 a) {
    float lo, hi;
    asm("mov.b64 {%0, %1}, %2;" : "=f"(lo), "=f"(hi) : "l"(a));
    return lo + hi;
}
// lane kc finalizes batch kc: keep own-batch partial, exchange partner's
__device__ __forceinline__ float xred(float b0, float b1, int kc) {
    float keep = kc ? b1 : b0;
    float send = kc ? b0 : b1;
    return keep + __shfl_xor_sync(0xffffffffu, send, 1);
}
__device__ __forceinline__ float sigf(float v)     { return __fdividef(1.f, 1.f + __expf(-v)); }
__device__ __forceinline__ float tanhfast(float v) { return 1.f - __fdividef(2.f, __expf(2.f * v) + 1.f); }

// 3 matrices x 2 batches, k-half (32) per thread, weights in registers.
__device__ __forceinline__ void dot6(const u64 (&wa)[16], const u64 (&wb)[16], const u64 (&wc)[16],
                                     const float* v, int kc36,
                                     u64 &a0, u64 &a1, u64 &a2, u64 &c0, u64 &c1, u64 &c2)
{
    const ulonglong2* h0 = reinterpret_cast<const ulonglong2*>(v + kc36);
    const ulonglong2* h1 = reinterpret_cast<const ulonglong2*>(v + 72 + kc36);
#pragma unroll
    for (int m = 0; m < 8; ++m) {
        ulonglong2 x0 = h0[m], x1 = h1[m];
        ffma2(a0, wa[2*m], x0.x); ffma2(a0, wa[2*m+1], x0.y);
        ffma2(a1, wb[2*m], x0.x); ffma2(a1, wb[2*m+1], x0.y);
        ffma2(a2, wc[2*m], x0.x); ffma2(a2, wc[2*m+1], x0.y);
        ffma2(c0, wa[2*m], x1.x); ffma2(c0, wa[2*m+1], x1.y);
        ffma2(c1, wb[2*m], x1.x); ffma2(c1, wb[2*m+1], x1.y);
        ffma2(c2, wc[2*m], x1.x); ffma2(c2, wc[2*m+1], x1.y);
    }
}

__global__ __launch_bounds__(384, 1)
void solar_fused(const float* __restrict__ x,
                 const float* __restrict__ Wi1,  const float* __restrict__ bi1,
                 const float* __restrict__ Whr1, const float* __restrict__ Whz1,
                 const float* __restrict__ Whn1, const float* __restrict__ bhn1,
                 const float* __restrict__ Wi2,  const float* __restrict__ bi2,
                 const float* __restrict__ Whr2, const float* __restrict__ Whz2,
                 const float* __restrict__ Whn2, const float* __restrict__ bhn2,
                 const float* __restrict__ Wp,   const float* __restrict__ bp,
                 const float* __restrict__ Wa,   const float* __restrict__ ba,
                 const float* __restrict__ W1,   const float* __restrict__ b1,
                 const float* __restrict__ W2,   const float* __restrict__ b2,
                 const float* __restrict__ W3,   const float* __restrict__ b3,
                 const float* __restrict__ W4,   const float* __restrict__ b4,
                 float* __restrict__ out)
{
    __shared__ __align__(16) float sm[STOT];

    const int tid  = threadIdx.x;
    const int grp  = tid >> 7;       // 0: L1-GRU(+xi1), 1: xi2+xp+loader, 2: L2-GRU+attn
    const int g    = tid & 127;
    const int j    = g >> 1;         // 0..63
    const int kc   = g & 1;          // k-half / finalized batch
    const int kc8  = kc * 8;
    const int kc36 = kc * 36;
    const int lane = tid & 31;
    const int wg   = g >> 5;         // warp within group 0..3
    const int widx = kc * 72 + (j >> 5) * 36 + (j & 31); // (batch kc, elem j)

    // ---------- register-resident weights ----------
    u64 wA[16], wB[16], wC[16], wD[4];
    float cb0 = 0.f, cb1 = 0.f, cb2 = 0.f, cb3 = 0.f, cwa = 0.f, cba = 0.f;
    if (grp == 0) {
#pragma unroll
        for (int m = 0; m < 16; ++m) {
            int k = kc * 32 + 2 * m;
            wA[m] = pack2(Whr1[k*64 + j], Whr1[(k+1)*64 + j]);
            wB[m] = pack2(Whz1[k*64 + j], Whz1[(k+1)*64 + j]);
            wC[m] = pack2(Whn1[k*64 + j], Whn1[(k+1)*64 + j]);
        }
        cb0 = bi1[j]; cb1 = bi1[64 + j]; cb2 = bi1[128 + j]; cb3 = bhn1[j];
    } else if (grp == 1) {
#pragma unroll
        for (int m = 0; m < 16; ++m) {
            int k = kc * 32 + 2 * m;
            wA[m] = pack2(Wi2[k*192 + j],       Wi2[(k+1)*192 + j]);
            wB[m] = pack2(Wi2[k*192 + 64 + j],  Wi2[(k+1)*192 + 64 + j]);
            wC[m] = pack2(Wi2[k*192 + 128 + j], Wi2[(k+1)*192 + 128 + j]);
        }
#pragma unroll
        for (int m = 0; m < 4; ++m) {
            int f = kc * 8 + 2 * m;
            wD[m] = pack2(Wp[f*64 + j], Wp[(f+1)*64 + j]);
        }
        cb0 = bi2[j]; cb1 = bi2[64 + j]; cb2 = bi2[128 + j]; cb3 = bp[j];
    } else {
#pragma unroll
        for (int m = 0; m < 16; ++m) {
            int k = kc * 32 + 2 * m;
            wA[m] = pack2(Whr2[k*64 + j], Whr2[(k+1)*64 + j]);
            wB[m] = pack2(Whz2[k*64 + j], Whz2[(k+1)*64 + j]);
            wC[m] = pack2(Whn2[k*64 + j], Whn2[(k+1)*64 + j]);
        }
        cb0 = bhn2[j]; cwa = Wa[j]; cba = ba[0];
    }

    // ---------- shared setup: Wi1 + zero state ----------
    for (int idx = tid; idx < 3072; idx += 384) {      // [dot][j*2+kc][8]
        int d = idx >> 10, rem = idx & 1023;
        int jk = rem >> 3, fl = rem & 7;
        sm[SWI + idx] = Wi1[((jk & 1) * 8 + fl) * 192 + d * 64 + (jk >> 1)];
    }
    for (int idx = tid; idx < 576; idx += 384) sm[H1B + idx] = 0.f;   // h1+h2 both slots

    // ---------- x prologue: t=0..7 into xbuf, rx = x[8] ----------
    float rx = 0.f;
    size_t xbase = 0;
    if (grp == 1 && g < 32) {
        int b = g >> 4, f = g & 15;
        int bg = blockIdx.x * 2 + b;
        xbase = (size_t)bg * T_N * 16 + f;
#pragma unroll
        for (int t = 0; t < 8; ++t) sm[XBUF + t * 32 + b * 16 + f] = x[xbase + (size_t)t * 16];
        rx = x[xbase + 128];                           // t=8
    }
    __syncthreads();

    // xp[t=0..3] prologue (group 1)
    if (grp == 1) {
#pragma unroll
        for (int tt = 0; tt < 4; ++tt) {
            const float* xb = sm + XBUF + tt * 32;
            u64 p0 = 0, p1 = 0;
            const ulonglong2* xa = reinterpret_cast<const ulonglong2*>(xb + kc8);
            const ulonglong2* xc = reinterpret_cast<const ulonglong2*>(xb + 16 + kc8);
#pragma unroll
            for (int m = 0; m < 2; ++m) {
                ulonglong2 a = xa[m], c = xc[m];
                ffma2(p0, wD[2*m], a.x); ffma2(p0, wD[2*m+1], a.y);
                ffma2(p1, wD[2*m], c.x); ffma2(p1, wD[2*m+1], c.y);
            }
            sm[XPB + tt * 136 + kc * 68 + j] = xred(hsum2(p0), hsum2(p1), kc) + cb3;
        }
    }
    __syncthreads();

    // ---------- recurrence: g0 @ t=i, g1 xi2@t=i-4 / xp@t=i+4, g2 @ t=i-8 ----------
    float am = -3.0e38f, as_ = 0.f, aacc = 0.f, po2 = 0.f;

#pragma unroll 2
    for (int i = 0; i <= T_N + 8; ++i) {
        if (grp == 0) {
            if (i < T_N) {
                int slot = i & 1;
                // input-side contributions first (independent of h -> overlap LDS latency)
                u64 r0=0, z0=0, nh0=0, r1=0, z1=0, nh1=0, ni0=0, ni1=0;
                {
                    const float* xb = sm + XBUF + (i & 15) * 32;
                    const ulonglong2* x0p = reinterpret_cast<const ulonglong2*>(xb + kc8);
                    const ulonglong2* x1p = reinterpret_cast<const ulonglong2*>(xb + 16 + kc8);
                    const ulonglong2* wiR = reinterpret_cast<const ulonglong2*>(sm + SWI + (j*2+kc)*8);
                    const ulonglong2* wiZ = reinterpret_cast<const ulonglong2*>(sm + SWI + 1024 + (j*2+kc)*8);
                    const ulonglong2* wiN = reinterpret_cast<const ulonglong2*>(sm + SWI + 2048 + (j*2+kc)*8);
#pragma unroll
                    for (int m = 0; m < 2; ++m) {
                        ulonglong2 xa = x0p[m], xc = x1p[m];
                        ulonglong2 wr = wiR[m], wz = wiZ[m], wn = wiN[m];
                        ffma2(r0,  wr.x, xa.x); ffma2(r0,  wr.y, xa.y);
                        ffma2(z0,  wz.x, xa.x); ffma2(z0,  wz.y, xa.y);
                        ffma2(ni0, wn.x, xa.x); ffma2(ni0, wn.y, xa.y);
                        ffma2(r1,  wr.x, xc.x); ffma2(r1,  wr.y, xc.y);
                        ffma2(z1,  wz.x, xc.x); ffma2(z1,  wz.y, xc.y);
                        ffma2(ni1, wn.x, xc.x); ffma2(ni1, wn.y, xc.y);
                    }
                }
                const float* hv = sm + H1B + slot * 144;
                dot6(wA, wB, wC, hv, kc36, r0, z0, nh0, r1, z1, nh1);
                float fR  = xred(hsum2(r0),  hsum2(r1),  kc);
                float fZ  = xred(hsum2(z0),  hsum2(z1),  kc);
                float fNH = xred(hsum2(nh0), hsum2(nh1), kc);
                float fNI = xred(hsum2(ni0), hsum2(ni1), kc);
                float r  = sigf(fR + cb0);
                float z  = sigf(fZ + cb1);
                float n  = tanhfast(fNI + cb2 + r * (fNH + cb3));
                float hp = sm[H1B + slot * 144 + widx];
                float hn = n + z * (hp - n);
                float xp = sm[XPB + (i & 7) * 136 + kc * 68 + j];
                sm[H1B + (slot ^ 1) * 144 + widx] = hn;
                sm[O1B + (i & 15) * 144 + widx]   = hn + 0.5f * xp;
            }
            NBAR(1);
        } else if (grp == 1) {
            if (i >= 4 && i <= T_N + 3) {     // xi2[t=i-4] = o1[i-4] @ Wi2 + bi2
                const float* ov = sm + O1B + ((i + 12) & 15) * 144;
                u64 a0=0, a1=0, a2=0, c0=0, c1=0, c2=0;
                dot6(wA, wB, wC, ov, kc36, a0, a1, a2, c0, c1, c2);
                float fR = xred(hsum2(a0), hsum2(c0), kc) + cb0;
                float fZ = xred(hsum2(a1), hsum2(c1), kc) + cb1;
                float fN = xred(hsum2(a2), hsum2(c2), kc) + cb2;
                int base = XI2B + ((i + 4) & 7) * 392 + kc * 196;
                sm[base + j]       = fR;
                sm[base + 64 + j]  = fZ;
                sm[base + 128 + j] = fN;
            }
            if (i <= T_N - 5) {               // xp[t=i+4]
                const float* xb = sm + XBUF + ((i + 4) & 15) * 32;
                u64 p0 = 0, p1 = 0;
                const ulonglong2* xa = reinterpret_cast<const ulonglong2*>(xb + kc8);
                const ulonglong2* xc = reinterpret_cast<const ulonglong2*>(xb + 16 + kc8);
#pragma unroll
                for (int m = 0; m < 2; ++m) {
                    ulonglong2 a = xa[m], c = xc[m];
                    ffma2(p0, wD[2*m], a.x); ffma2(p0, wD[2*m+1], a.y);
                    ffma2(p1, wD[2*m], c.x); ffma2(p1, wD[2*m+1], c.y);
                }
                sm[XPB + ((i + 4) & 7) * 136 + kc * 68 + j] = xred(hsum2(p0), hsum2(p1), kc) + cb3;
            }
            if (g < 32) {                     // x stream: store t=i+8, prefetch t=i+9
                if (i <= T_N - 9)  sm[XBUF + ((i + 8) & 15) * 32 + (g >> 4) * 16 + (g & 15)] = rx;
                if (i <= T_N - 10) rx = x[xbase + (size_t)(i + 9) * 16];
            }
            // no barrier: all g1 dependencies are epoch-protected (skew >= 4)
        } else {
            if (i >= 9) {                     // online softmax for t = i-9
                float4 sp = *reinterpret_cast<const float4*>(sm + SCB + ((i - 1) & 1) * 8 + kc * 4);
                float sc   = (sp.x + sp.y) + (sp.z + sp.w) + cba;
                float nm   = fmaxf(am, sc);
                float corr = __expf(am - nm);
                float p    = __expf(sc - nm);
                as_  = as_  * corr + p;
                aacc = aacc * corr + p * po2;
                am   = nm;
            }
            if (i >= 8 && i <= T_N + 7) {     // layer-2 GRU for t = i-8
                int hs = i & 1;
                const float* hv = sm + H2B + hs * 144;
                u64 a0=0, a1=0, a2=0, c0=0, c1=0, c2=0;
                dot6(wA, wB, wC, hv, kc36, a0, a1, a2, c0, c1, c2);
                float fR  = xred(hsum2(a0), hsum2(c0), kc);
                float fZ  = xred(hsum2(a1), hsum2(c1), kc);
                float fNH = xred(hsum2(a2), hsum2(c2), kc);
                int xb2 = XI2B + (i & 7) * 392 + kc * 196;
                float ir = sm[xb2 + j], iz = sm[xb2 + 64 + j], inn = sm[xb2 + 128 + j];
                float hp = sm[H2B + hs * 144 + widx];
                float r  = sigf(ir + fR);
                float z  = sigf(iz + fZ);
                float n  = tanhfast(inn + r * (fNH + cb0));
                float hn = n + z * (hp - n);
                float o1r = sm[O1B + ((i + 8) & 15) * 144 + widx];
                float o2  = hn + 0.5f * o1r;
                po2 = o2;
                sm[H2B + (hs ^ 1) * 144 + widx] = hn;
                float part = o2 * cwa;        // score partial for batch kc
                part += __shfl_xor_sync(0xffffffffu, part, 2);
                part += __shfl_xor_sync(0xffffffffu, part, 4);
                part += __shfl_xor_sync(0xffffffffu, part, 8);
                part += __shfl_xor_sync(0xffffffffu, part, 16);
                if (lane < 2) sm[SCB + (i & 1) * 8 + kc * 4 + wg] = part;
            }
            NBAR(3);
        }
        if ((i & 3) == 3) __syncthreads();    // all cross-group deps have skew >= 4
    }
    __syncthreads();

    // ---------- attention finalize + MLP head ----------
    if (grp == 2) sm[SATT + kc * 64 + j] = aacc / as_;
    __syncthreads();

    if (tid < 256) {
        int b = tid >> 7, o = tid & 127;
        float acc = b1[o];
        const float* av = sm + SATT + b * 64;
#pragma unroll 8
        for (int k = 0; k < 64; ++k) acc += av[k] * W1[k * 128 + o];
        sm[SM1 + b * 128 + o] = fmaxf(acc, 0.f);
    }
    __syncthreads();
    if (tid < 128) {
        int b = tid >> 6, o = tid & 63;
        float acc = b2[o];
        const float* av = sm + SM1 + b * 128;
#pragma unroll 8
        for (int k = 0; k < 128; ++k) acc += av[k] * W2[k * 64 + o];
        sm[SM2 + b * 64 + o] = fmaxf(acc, 0.f);
    }
    __syncthreads();
    if (tid < 64) {
        int b = tid >> 5, o = tid & 31;
        float acc = b3[o];
        const float* av = sm + SM2 + b * 64;
#pragma unroll 8
        for (int k = 0; k < 64; ++k) acc += av[k] * W3[k * 32 + o];
        sm[SM3 + b * 32 + o] = fmaxf(acc, 0.f);
    }
    __syncthreads();
    if (tid < 4) {
        int b = tid >> 1, o = tid & 1;
        float acc = b4[o];
        const float* av = sm + SM3 + b * 32;
#pragma unroll
        for (int k = 0; k < 32; ++k) acc += av[k] * W4[k * 2 + o];
        out[((size_t)blockIdx.x * 2 + b) * 2 + o] = acc;
    }
}

extern "C" void kernel_launch(void* const* d_in, const int* in_sizes, int n_in,
                              void* d_out, int out_size) {
    (void)in_sizes; (void)n_in; (void)out_size;
    const float* x    = (const float*)d_in[0];
    const float* Wi1  = (const float*)d_in[1];
    const float* bi1  = (const float*)d_in[2];
    const float* Whr1 = (const float*)d_in[3];
    const float* Whz1 = (const float*)d_in[4];
    const float* Whn1 = (const float*)d_in[5];
    const float* bhn1 = (const float*)d_in[6];
    const float* Wi2  = (const float*)d_in[7];
    const float* bi2  = (const float*)d_in[8];
    const float* Whr2 = (const float*)d_in[9];
    const float* Whz2 = (const float*)d_in[10];
    const float* Whn2 = (const float*)d_in[11];
    const float* bhn2 = (const float*)d_in[12];
    const float* Wp   = (const float*)d_in[13];
    const float* bp   = (const float*)d_in[14];
    const float* Wa   = (const float*)d_in[15];
    const float* ba   = (const float*)d_in[16];
    const float* W1   = (const float*)d_in[17];
    const float* b1   = (const float*)d_in[18];
    const float* W2   = (const float*)d_in[19];
    const float* b2   = (const float*)d_in[20];
    const float* W3   = (const float*)d_in[21];
    const float* b3   = (const float*)d_in[22];
    const float* W4   = (const float*)d_in[23];
    const float* b4   = (const float*)d_in[24];
    float* out = (float*)d_out;

    solar_fused<<<128, 384>>>(x, Wi1, bi1, Whr1, Whz1, Whn1, bhn1,
                              Wi2, bi2, Whr2, Whz2, Whn2, bhn2,
                              Wp, bp, Wa, ba,
                              W1, b1, W2, b2, W3, b3, W4, b4, out);
}